// round 1
// baseline (speedup 1.0000x reference)
#include <cuda_runtime.h>

#define BB 8
#define NN 4096
#define DD 64
#define KK 20
#define CC 64
#define MM (BB*NN)          // 32768 points
#define PTS (MM*KK)         // 655360 (point, neighbor) pairs
#define CNT (NN*KK)         // 81920 values per (b, c) for instance norm
#define EPSN 1e-5f
#define SLOPE 0.01f
#define GS 324              // padded point-stride for transposed g tile
#define HS 68               // padded channel-stride for h3 tile

// ---------------- device scratch (static: allocation-free) ----------------
__device__ float d_P[MM*CC];        // x_flat @ W1a^T            (8 MB)
__device__ float d_U[MM*CC];        // x_flat @ (W1b - W1a)^T    (8 MB)
__device__ float d_h2[(size_t)PTS*CC];  // stage-2 pre-norm       (167 MB)
__device__ float d_h3max[MM*CC];    // max_k of pre-norm h3      (8 MB)
__device__ float d_stats[6*BB*CC];  // [sum1,sq1,sum2,sq2,sum3,sq3]
__device__ int   d_is64;

__device__ __forceinline__ float leaky(float v){ return fmaxf(v, SLOPE*v); }

__device__ __forceinline__ int load_ind(const void* ind, int p, int is64){
    if (is64) return (int)((const long long*)ind)[p];
    return ((const int*)ind)[p];
}

// ---------------- K_init: zero stats ----------------
__global__ void k_init(){
    int t = blockIdx.x*blockDim.x + threadIdx.x;
    if (t < 6*BB*CC) d_stats[t] = 0.f;
}

// ---------------- K_detect: int32 vs int64 indices ----------------
__global__ void k_detect(const int* ind32){
    if (threadIdx.x == 0 && blockIdx.x == 0){
        int is64 = 1;
        for (int i = 0; i < 128; i++){
            if (ind32[2*i + 1] != 0){ is64 = 0; break; }
        }
        d_is64 = is64;
    }
}

// ---------------- K0: P = x@W1a^T, U = x@(W1b-W1a)^T ----------------
// grid 512, block (16,16), tile 64 rows x 64 cols, 4x4 per thread
__global__ void __launch_bounds__(256) k0(const float* __restrict__ x,
                                          const float* __restrict__ W1){
    extern __shared__ float sm[];
    float* xT = sm;             // 64 x 68
    float* Wa = sm + 64*68;     // [d][c]
    float* Wd = Wa + 4096;      // [d][c] = W1b - W1a

    int tid = threadIdx.y*16 + threadIdx.x;
    int m0  = blockIdx.x*64;

    for (int i = tid; i < 4096; i += 256){
        int c = i >> 6, d = i & 63;
        float a = W1[c*128 + d];
        float b = W1[c*128 + 64 + d];
        Wa[d*64 + c] = a;
        Wd[d*64 + c] = b - a;
    }
    for (int i = tid; i < 1024; i += 256){
        int r = i >> 4, c4 = i & 15;
        float4 v = *(const float4*)(x + (m0 + r)*64 + c4*4);
        xT[(c4*4+0)*68 + r] = v.x;
        xT[(c4*4+1)*68 + r] = v.y;
        xT[(c4*4+2)*68 + r] = v.z;
        xT[(c4*4+3)*68 + r] = v.w;
    }
    __syncthreads();

    int c0 = threadIdx.x*4, r0 = threadIdx.y*4;
    float accP[4][4], accU[4][4];
    #pragma unroll
    for (int i=0;i<4;i++)
        #pragma unroll
        for (int j=0;j<4;j++){ accP[i][j]=0.f; accU[i][j]=0.f; }

    for (int d = 0; d < 64; d++){
        float4 xv = *(const float4*)(xT + d*68 + r0);
        float4 wa = *(const float4*)(Wa + d*64 + c0);
        float4 wd = *(const float4*)(Wd + d*64 + c0);
        float xs[4] = {xv.x, xv.y, xv.z, xv.w};
        float was[4] = {wa.x, wa.y, wa.z, wa.w};
        float wds[4] = {wd.x, wd.y, wd.z, wd.w};
        #pragma unroll
        for (int i=0;i<4;i++)
            #pragma unroll
            for (int j=0;j<4;j++){
                accP[i][j] += xs[i]*was[j];
                accU[i][j] += xs[i]*wds[j];
            }
    }
    #pragma unroll
    for (int i=0;i<4;i++){
        int row = (m0 + r0 + i)*64 + c0;
        *(float4*)(d_P + row) = make_float4(accP[i][0],accP[i][1],accP[i][2],accP[i][3]);
        *(float4*)(d_U + row) = make_float4(accU[i][0],accU[i][1],accU[i][2],accU[i][3]);
    }
}

// ---------------- K1: stage-1 stats (sum, sumsq of h1 = P[idx]+U[m]) ----------------
// grid 1024 x 256 threads; 640 points per block (batch-aligned: 128 blocks/batch)
__global__ void __launch_bounds__(256) k1(const void* __restrict__ ind_){
    __shared__ float ssum[64], ssq[64];
    int tid = threadIdx.x;
    int blk = blockIdx.x;
    int b   = blk >> 7;
    int is64 = d_is64;
    int c4 = tid & 15, slot = tid >> 4;   // 16 point-slots in flight
    int pbase = blk*640;

    float s[4] = {0,0,0,0}, s2[4] = {0,0,0,0};
    for (int it = 0; it < 40; it++){
        int gp = pbase + it*16 + slot;
        int idx = load_ind(ind_, gp, is64);
        int m = gp / KK;
        float4 pv = *(const float4*)(d_P + idx*64 + c4*4);
        float4 uv = *(const float4*)(d_U + m*64 + c4*4);
        float h[4] = {pv.x+uv.x, pv.y+uv.y, pv.z+uv.z, pv.w+uv.w};
        #pragma unroll
        for (int q=0;q<4;q++){ s[q] += h[q]; s2[q] += h[q]*h[q]; }
    }
    if (tid < 64){ ssum[tid] = 0.f; ssq[tid] = 0.f; }
    __syncthreads();
    #pragma unroll
    for (int q=0;q<4;q++){
        atomicAdd(&ssum[c4*4+q], s[q]);
        atomicAdd(&ssq [c4*4+q], s2[q]);
    }
    __syncthreads();
    if (tid < 64){
        atomicAdd(&d_stats[0*512 + b*64 + tid], ssum[tid]);
        atomicAdd(&d_stats[1*512 + b*64 + tid], ssq[tid]);
    }
    (void)b;
}

// ---------------- K2: regather h1 -> norm1 -> leaky -> @W2^T -> h2 + stats2 ----------------
// grid 2048, block (8,40)=320 thr, tile 320 points x 64 ch, per-thread 8x8
__global__ void __launch_bounds__(320,2) k2(const void* __restrict__ ind_,
                                            const float* __restrict__ W2){
    extern __shared__ float sm[];
    float* w_s    = sm;                 // 4096: W2 transposed [d][c]
    float* gbuf   = sm + 4096;          // 21760 floats; uses 64*GS here
    float* mean_s = sm + 4096 + 21760;
    float* rstd_s = mean_s + 64;
    float* ssum   = rstd_s + 64;
    float* ssq    = ssum + 64;

    int tx = threadIdx.x, ty = threadIdx.y;
    int tid = ty*8 + tx;
    int blk = blockIdx.x;
    int b   = blk >> 8;                 // 256 blocks per batch
    int is64 = d_is64;
    int pbase = blk*320;

    for (int i = tid; i < 4096; i += 320){
        int c = i >> 6, d = i & 63;
        w_s[d*64 + c] = W2[i];
    }
    if (tid < 64){
        float s  = d_stats[0*512 + b*64 + tid];
        float s2 = d_stats[1*512 + b*64 + tid];
        float mu = s * (1.f/(float)CNT);
        float var = s2 * (1.f/(float)CNT) - mu*mu;
        mean_s[tid] = mu;
        rstd_s[tid] = rsqrtf(var + EPSN);
        ssum[tid] = 0.f; ssq[tid] = 0.f;
    }
    __syncthreads();

    // fill normalized+activated g, transposed [c][p]
    {
        int c4 = tid & 15, slot = tid >> 4;   // 20 slots
        for (int it = 0; it < 16; it++){
            int p  = it*20 + slot;
            int gp = pbase + p;
            int idx = load_ind(ind_, gp, is64);
            int m = gp / KK;
            float4 pv = *(const float4*)(d_P + idx*64 + c4*4);
            float4 uv = *(const float4*)(d_U + m*64 + c4*4);
            float h[4] = {pv.x+uv.x, pv.y+uv.y, pv.z+uv.z, pv.w+uv.w};
            #pragma unroll
            for (int q=0;q<4;q++){
                int c = c4*4+q;
                gbuf[c*GS + p] = leaky((h[q]-mean_s[c])*rstd_s[c]);
            }
        }
    }
    __syncthreads();

    int c0 = tx*8, p0 = ty*8;
    float acc[8][8];
    #pragma unroll
    for (int i=0;i<8;i++)
        #pragma unroll
        for (int j=0;j<8;j++) acc[i][j] = 0.f;

    for (int d = 0; d < 64; d++){
        float4 g0 = *(const float4*)(gbuf + d*GS + p0);
        float4 g1 = *(const float4*)(gbuf + d*GS + p0 + 4);
        float4 w0 = *(const float4*)(w_s + d*64 + c0);
        float4 w1 = *(const float4*)(w_s + d*64 + c0 + 4);
        float gg[8] = {g0.x,g0.y,g0.z,g0.w,g1.x,g1.y,g1.z,g1.w};
        float ww[8] = {w0.x,w0.y,w0.z,w0.w,w1.x,w1.y,w1.z,w1.w};
        #pragma unroll
        for (int i=0;i<8;i++)
            #pragma unroll
            for (int j=0;j<8;j++) acc[i][j] += gg[i]*ww[j];
    }

    float s[8], s2[8];
    #pragma unroll
    for (int j=0;j<8;j++){ s[j]=0.f; s2[j]=0.f; }
    #pragma unroll
    for (int i=0;i<8;i++){
        int gp = pbase + p0 + i;
        *(float4*)(d_h2 + (size_t)gp*64 + c0)     = make_float4(acc[i][0],acc[i][1],acc[i][2],acc[i][3]);
        *(float4*)(d_h2 + (size_t)gp*64 + c0 + 4) = make_float4(acc[i][4],acc[i][5],acc[i][6],acc[i][7]);
        #pragma unroll
        for (int j=0;j<8;j++){ float v = acc[i][j]; s[j]+=v; s2[j]+=v*v; }
    }
    #pragma unroll
    for (int j=0;j<8;j++){
        atomicAdd(&ssum[c0+j], s[j]);
        atomicAdd(&ssq [c0+j], s2[j]);
    }
    __syncthreads();
    if (tid < 64){
        atomicAdd(&d_stats[2*512 + b*64 + tid], ssum[tid]);
        atomicAdd(&d_stats[3*512 + b*64 + tid], ssq[tid]);
    }
}

// ---------------- K3: h2 -> norm2 -> leaky -> @W3^T -> stats3 + max over k ----------------
__global__ void __launch_bounds__(320,2) k3(const float* __restrict__ W3){
    extern __shared__ float sm[];
    float* w_s    = sm;
    float* gbuf   = sm + 4096;          // matmul: 64*GS; then reused as hs: 320*HS
    float* mean_s = sm + 4096 + 21760;
    float* rstd_s = mean_s + 64;
    float* ssum   = rstd_s + 64;
    float* ssq    = ssum + 64;

    int tx = threadIdx.x, ty = threadIdx.y;
    int tid = ty*8 + tx;
    int blk = blockIdx.x;
    int b   = blk >> 8;
    int pbase = blk*320;

    for (int i = tid; i < 4096; i += 320){
        int c = i >> 6, d = i & 63;
        w_s[d*64 + c] = W3[i];
    }
    if (tid < 64){
        float s  = d_stats[2*512 + b*64 + tid];
        float s2 = d_stats[3*512 + b*64 + tid];
        float mu = s * (1.f/(float)CNT);
        float var = s2 * (1.f/(float)CNT) - mu*mu;
        mean_s[tid] = mu;
        rstd_s[tid] = rsqrtf(var + EPSN);
        ssum[tid] = 0.f; ssq[tid] = 0.f;
    }
    __syncthreads();

    {
        int c4 = tid & 15, slot = tid >> 4;
        for (int it = 0; it < 16; it++){
            int p  = it*20 + slot;
            int gp = pbase + p;
            float4 hv = *(const float4*)(d_h2 + (size_t)gp*64 + c4*4);
            float h[4] = {hv.x, hv.y, hv.z, hv.w};
            #pragma unroll
            for (int q=0;q<4;q++){
                int c = c4*4+q;
                gbuf[c*GS + p] = leaky((h[q]-mean_s[c])*rstd_s[c]);
            }
        }
    }
    __syncthreads();

    int c0 = tx*8, p0 = ty*8;
    float acc[8][8];
    #pragma unroll
    for (int i=0;i<8;i++)
        #pragma unroll
        for (int j=0;j<8;j++) acc[i][j] = 0.f;

    for (int d = 0; d < 64; d++){
        float4 g0 = *(const float4*)(gbuf + d*GS + p0);
        float4 g1 = *(const float4*)(gbuf + d*GS + p0 + 4);
        float4 w0 = *(const float4*)(w_s + d*64 + c0);
        float4 w1 = *(const float4*)(w_s + d*64 + c0 + 4);
        float gg[8] = {g0.x,g0.y,g0.z,g0.w,g1.x,g1.y,g1.z,g1.w};
        float ww[8] = {w0.x,w0.y,w0.z,w0.w,w1.x,w1.y,w1.z,w1.w};
        #pragma unroll
        for (int i=0;i<8;i++)
            #pragma unroll
            for (int j=0;j<8;j++) acc[i][j] += gg[i]*ww[j];
    }

    float s[8], s2[8];
    #pragma unroll
    for (int j=0;j<8;j++){ s[j]=0.f; s2[j]=0.f; }
    #pragma unroll
    for (int i=0;i<8;i++)
        #pragma unroll
        for (int j=0;j<8;j++){ float v = acc[i][j]; s[j]+=v; s2[j]+=v*v; }

    __syncthreads();   // all gbuf reads done before overwrite as hs

    #pragma unroll
    for (int i=0;i<8;i++){
        int p = p0 + i;
        *(float4*)(gbuf + p*HS + c0)     = make_float4(acc[i][0],acc[i][1],acc[i][2],acc[i][3]);
        *(float4*)(gbuf + p*HS + c0 + 4) = make_float4(acc[i][4],acc[i][5],acc[i][6],acc[i][7]);
    }
    #pragma unroll
    for (int j=0;j<8;j++){
        atomicAdd(&ssum[c0+j], s[j]);
        atomicAdd(&ssq [c0+j], s2[j]);
    }
    __syncthreads();

    if (tid < 64){
        atomicAdd(&d_stats[4*512 + b*64 + tid], ssum[tid]);
        atomicAdd(&d_stats[5*512 + b*64 + tid], ssq[tid]);
    }

    // max over k=20 within each of the 16 (b,n) groups of this block (pre-norm: monotone)
    for (int o = tid; o < 16*64; o += 320){
        int gi = o >> 6, c = o & 63;
        float mx = gbuf[(gi*20)*HS + c];
        #pragma unroll
        for (int j = 1; j < 20; j++)
            mx = fmaxf(mx, gbuf[(gi*20 + j)*HS + c]);
        d_h3max[(blk*16 + gi)*64 + c] = mx;
    }
}

// ---------------- K4: norm3 + leaky on maxed h3 -> output ----------------
__global__ void __launch_bounds__(256) k4(float* __restrict__ out){
    int g = blockIdx.x*256 + threadIdx.x;
    int c = g & 63;
    int b = g >> 18;                    // N*C = 262144 = 2^18 per batch
    float s  = d_stats[4*512 + b*64 + c];
    float s2 = d_stats[5*512 + b*64 + c];
    float mu = s * (1.f/(float)CNT);
    float var = s2 * (1.f/(float)CNT) - mu*mu;
    float r = rsqrtf(var + EPSN);
    out[g] = leaky((d_h3max[g] - mu)*r);
}

// ---------------- launch ----------------
extern "C" void kernel_launch(void* const* d_in, const int* in_sizes, int n_in,
                              void* d_out, int out_size){
    const float* x   = (const float*)d_in[0];
    const void*  ind = d_in[1];
    const float* W1  = (const float*)d_in[2];
    const float* W2  = (const float*)d_in[3];
    const float* W3  = (const float*)d_in[4];

    cudaFuncSetAttribute(k0, cudaFuncAttributeMaxDynamicSharedMemorySize, 50176);
    cudaFuncSetAttribute(k2, cudaFuncAttributeMaxDynamicSharedMemorySize, 104448);
    cudaFuncSetAttribute(k3, cudaFuncAttributeMaxDynamicSharedMemorySize, 104448);

    k_init  <<<6, 512>>>();
    k_detect<<<1, 32>>>((const int*)ind);
    k0      <<<512, dim3(16,16), 50176>>>(x, W1);
    k1      <<<1024, 256>>>(ind);
    k2      <<<2048, dim3(8,40), 104448>>>(ind, W2);
    k3      <<<2048, dim3(8,40), 104448>>>(W3);
    k4      <<<8192, 256>>>((float*)d_out);

    (void)in_sizes; (void)n_in; (void)out_size;
}

// round 2
// speedup vs baseline: 1.0418x; 1.0418x over previous
#include <cuda_runtime.h>

#define BB 8
#define NN 4096
#define DD 64
#define KK 20
#define CC 64
#define MM (BB*NN)          // 32768 points
#define PTS (MM*KK)         // 655360 (point, neighbor) pairs
#define CNT (NN*KK)         // 81920 values per (b, c) for instance norm
#define EPSN 1e-5f
#define SLOPE 0.01f
#define GS 324              // padded point-stride for transposed g tile
#define HS 68               // padded channel-stride for h3 tile

// ---------------- device scratch (static: allocation-free) ----------------
__device__ float d_P[MM*CC];        // x_flat @ W1a^T            (8 MB)
__device__ float d_U[MM*CC];        // x_flat @ (W1b - W1a)^T    (8 MB)
__device__ float d_h2[(size_t)PTS*CC];  // stage-2 pre-norm       (167 MB)
__device__ float d_h3max[MM*CC];    // max_k of pre-norm h3      (8 MB)
__device__ float d_stats[6*BB*CC];  // [sum1,sq1,sum2,sq2,sum3,sq3]
__device__ int   d_is64;

__device__ __forceinline__ float leaky(float v){ return fmaxf(v, SLOPE*v); }

__device__ __forceinline__ int load_ind(const void* ind, int p, int is64){
    if (is64) return (int)((const long long*)ind)[p];
    return ((const int*)ind)[p];
}

// ---- packed fp32x2 helpers (sm_100+): double-rate fp32 FMA, exact rn rounding ----
__device__ __forceinline__ unsigned long long ffma2(unsigned long long a,
                                                    unsigned long long b,
                                                    unsigned long long c){
    unsigned long long d;
    asm("fma.rn.f32x2 %0, %1, %2, %3;" : "=l"(d) : "l"(a), "l"(b), "l"(c));
    return d;
}
__device__ __forceinline__ unsigned long long dup2(float v){
    unsigned long long d;
    asm("mov.b64 %0, {%1, %1};" : "=l"(d) : "f"(v));
    return d;
}
__device__ __forceinline__ void unpack2(unsigned long long p, float& lo, float& hi){
    asm("mov.b64 {%0, %1}, %2;" : "=f"(lo), "=f"(hi) : "l"(p));
}

// ---------------- K_init: zero stats ----------------
__global__ void k_init(){
    int t = blockIdx.x*blockDim.x + threadIdx.x;
    if (t < 6*BB*CC) d_stats[t] = 0.f;
}

// ---------------- K_detect: int32 vs int64 indices ----------------
__global__ void k_detect(const int* ind32){
    if (threadIdx.x == 0 && blockIdx.x == 0){
        int is64 = 1;
        for (int i = 0; i < 128; i++){
            if (ind32[2*i + 1] != 0){ is64 = 0; break; }
        }
        d_is64 = is64;
    }
}

// ---------------- K0: P = x@W1a^T, U = x@(W1b-W1a)^T ----------------
__global__ void __launch_bounds__(256) k0(const float* __restrict__ x,
                                          const float* __restrict__ W1){
    extern __shared__ float sm[];
    float* xT = sm;             // 64 x 68
    float* Wa = sm + 64*68;     // [d][c]
    float* Wd = Wa + 4096;      // [d][c] = W1b - W1a

    int tid = threadIdx.y*16 + threadIdx.x;
    int m0  = blockIdx.x*64;

    for (int i = tid; i < 4096; i += 256){
        int c = i >> 6, d = i & 63;
        float a = W1[c*128 + d];
        float b = W1[c*128 + 64 + d];
        Wa[d*64 + c] = a;
        Wd[d*64 + c] = b - a;
    }
    for (int i = tid; i < 1024; i += 256){
        int r = i >> 4, c4 = i & 15;
        float4 v = *(const float4*)(x + (m0 + r)*64 + c4*4);
        xT[(c4*4+0)*68 + r] = v.x;
        xT[(c4*4+1)*68 + r] = v.y;
        xT[(c4*4+2)*68 + r] = v.z;
        xT[(c4*4+3)*68 + r] = v.w;
    }
    __syncthreads();

    int c0 = threadIdx.x*4, r0 = threadIdx.y*4;
    // packed: 4 rows x 2 channel-pairs for P and U
    unsigned long long accP[4][2], accU[4][2];
    #pragma unroll
    for (int i=0;i<4;i++){ accP[i][0]=0ULL; accP[i][1]=0ULL; accU[i][0]=0ULL; accU[i][1]=0ULL; }

    for (int d = 0; d < 64; d++){
        float4 xv = *(const float4*)(xT + d*68 + r0);
        ulonglong2 wa = *(const ulonglong2*)(Wa + d*64 + c0);
        ulonglong2 wd = *(const ulonglong2*)(Wd + d*64 + c0);
        float xs[4] = {xv.x, xv.y, xv.z, xv.w};
        #pragma unroll
        for (int i=0;i<4;i++){
            unsigned long long xd = dup2(xs[i]);
            accP[i][0] = ffma2(xd, wa.x, accP[i][0]);
            accP[i][1] = ffma2(xd, wa.y, accP[i][1]);
            accU[i][0] = ffma2(xd, wd.x, accU[i][0]);
            accU[i][1] = ffma2(xd, wd.y, accU[i][1]);
        }
    }
    #pragma unroll
    for (int i=0;i<4;i++){
        int row = (m0 + r0 + i)*64 + c0;
        float p0,p1,p2,p3,u0,u1,u2,u3;
        unpack2(accP[i][0], p0, p1); unpack2(accP[i][1], p2, p3);
        unpack2(accU[i][0], u0, u1); unpack2(accU[i][1], u2, u3);
        *(float4*)(d_P + row) = make_float4(p0,p1,p2,p3);
        *(float4*)(d_U + row) = make_float4(u0,u1,u2,u3);
    }
}

// ---------------- K1: stage-1 stats (sum, sumsq of h1 = P[idx]+U[m]) ----------------
__global__ void __launch_bounds__(256) k1(const void* __restrict__ ind_){
    __shared__ float ssum[64], ssq[64];
    int tid = threadIdx.x;
    int blk = blockIdx.x;
    int b   = blk >> 7;
    int is64 = d_is64;
    int c4 = tid & 15, slot = tid >> 4;   // 16 point-slots in flight
    int pbase = blk*640;

    float s[4] = {0,0,0,0}, s2[4] = {0,0,0,0};
    for (int it = 0; it < 40; it++){
        int gp = pbase + it*16 + slot;
        int idx = load_ind(ind_, gp, is64);
        int m = gp / KK;
        float4 pv = *(const float4*)(d_P + idx*64 + c4*4);
        float4 uv = *(const float4*)(d_U + m*64 + c4*4);
        float h[4] = {pv.x+uv.x, pv.y+uv.y, pv.z+uv.z, pv.w+uv.w};
        #pragma unroll
        for (int q=0;q<4;q++){ s[q] += h[q]; s2[q] += h[q]*h[q]; }
    }
    if (tid < 64){ ssum[tid] = 0.f; ssq[tid] = 0.f; }
    __syncthreads();
    #pragma unroll
    for (int q=0;q<4;q++){
        atomicAdd(&ssum[c4*4+q], s[q]);
        atomicAdd(&ssq [c4*4+q], s2[q]);
    }
    __syncthreads();
    if (tid < 64){
        atomicAdd(&d_stats[0*512 + b*64 + tid], ssum[tid]);
        atomicAdd(&d_stats[1*512 + b*64 + tid], ssq[tid]);
    }
}

// ---------------- K2: regather h1 -> norm1 -> leaky -> @W2^T -> h2 + stats2 ----------------
// grid 2048, block (8,40)=320 thr, tile 320 points x 64 ch, per-thread 8p x (4 ch-pairs)
__global__ void __launch_bounds__(320,2) k2(const void* __restrict__ ind_,
                                            const float* __restrict__ W2){
    extern __shared__ float sm[];
    float* w_s    = sm;                 // 4096: W2 transposed [d][c]
    float* gbuf   = sm + 4096;          // 64*GS transposed g tile
    float* mean_s = sm + 4096 + 21760;
    float* rstd_s = mean_s + 64;
    float* ssum   = rstd_s + 64;
    float* ssq    = ssum + 64;

    int tx = threadIdx.x, ty = threadIdx.y;
    int tid = ty*8 + tx;
    int blk = blockIdx.x;
    int b   = blk >> 8;                 // 256 blocks per batch
    int is64 = d_is64;
    int pbase = blk*320;

    for (int i = tid; i < 4096; i += 320){
        int c = i >> 6, d = i & 63;
        w_s[d*64 + c] = W2[i];
    }
    if (tid < 64){
        float s  = d_stats[0*512 + b*64 + tid];
        float s2 = d_stats[1*512 + b*64 + tid];
        float mu = s * (1.f/(float)CNT);
        float var = s2 * (1.f/(float)CNT) - mu*mu;
        mean_s[tid] = mu;
        rstd_s[tid] = rsqrtf(var + EPSN);
        ssum[tid] = 0.f; ssq[tid] = 0.f;
    }
    __syncthreads();

    // fill normalized+activated g, transposed [c][p]
    {
        int c4 = tid & 15, slot = tid >> 4;   // 20 slots
        for (int it = 0; it < 16; it++){
            int p  = it*20 + slot;
            int gp = pbase + p;
            int idx = load_ind(ind_, gp, is64);
            int m = gp / KK;
            float4 pv = *(const float4*)(d_P + idx*64 + c4*4);
            float4 uv = *(const float4*)(d_U + m*64 + c4*4);
            float h[4] = {pv.x+uv.x, pv.y+uv.y, pv.z+uv.z, pv.w+uv.w};
            #pragma unroll
            for (int q=0;q<4;q++){
                int c = c4*4+q;
                gbuf[c*GS + p] = leaky((h[q]-mean_s[c])*rstd_s[c]);
            }
        }
    }
    __syncthreads();

    int c0 = tx*8, p0 = ty*8;
    unsigned long long acc[8][4];
    #pragma unroll
    for (int i=0;i<8;i++)
        #pragma unroll
        for (int j=0;j<4;j++) acc[i][j] = 0ULL;

    for (int d = 0; d < 64; d++){
        float4 g0 = *(const float4*)(gbuf + d*GS + p0);
        float4 g1 = *(const float4*)(gbuf + d*GS + p0 + 4);
        ulonglong2 w0 = *(const ulonglong2*)(w_s + d*64 + c0);
        ulonglong2 w1 = *(const ulonglong2*)(w_s + d*64 + c0 + 4);
        float gg[8] = {g0.x,g0.y,g0.z,g0.w,g1.x,g1.y,g1.z,g1.w};
        #pragma unroll
        for (int i=0;i<8;i++){
            unsigned long long gd = dup2(gg[i]);
            acc[i][0] = ffma2(gd, w0.x, acc[i][0]);
            acc[i][1] = ffma2(gd, w0.y, acc[i][1]);
            acc[i][2] = ffma2(gd, w1.x, acc[i][2]);
            acc[i][3] = ffma2(gd, w1.y, acc[i][3]);
        }
    }

    float s[8], s2[8];
    #pragma unroll
    for (int j=0;j<8;j++){ s[j]=0.f; s2[j]=0.f; }
    #pragma unroll
    for (int i=0;i<8;i++){
        int gp = pbase + p0 + i;
        float v[8];
        #pragma unroll
        for (int j=0;j<4;j++) unpack2(acc[i][j], v[2*j], v[2*j+1]);
        *(float4*)(d_h2 + (size_t)gp*64 + c0)     = make_float4(v[0],v[1],v[2],v[3]);
        *(float4*)(d_h2 + (size_t)gp*64 + c0 + 4) = make_float4(v[4],v[5],v[6],v[7]);
        #pragma unroll
        for (int j=0;j<8;j++){ s[j]+=v[j]; s2[j]+=v[j]*v[j]; }
    }
    #pragma unroll
    for (int j=0;j<8;j++){
        atomicAdd(&ssum[c0+j], s[j]);
        atomicAdd(&ssq [c0+j], s2[j]);
    }
    __syncthreads();
    if (tid < 64){
        atomicAdd(&d_stats[2*512 + b*64 + tid], ssum[tid]);
        atomicAdd(&d_stats[3*512 + b*64 + tid], ssq[tid]);
    }
}

// ---------------- K3: h2 -> norm2 -> leaky -> @W3^T -> stats3 + max over k ----------------
__global__ void __launch_bounds__(320,2) k3(const float* __restrict__ W3){
    extern __shared__ float sm[];
    float* w_s    = sm;
    float* gbuf   = sm + 4096;          // matmul: 64*GS; then reused as hs: 320*HS
    float* mean_s = sm + 4096 + 21760;
    float* rstd_s = mean_s + 64;
    float* ssum   = rstd_s + 64;
    float* ssq    = ssum + 64;

    int tx = threadIdx.x, ty = threadIdx.y;
    int tid = ty*8 + tx;
    int blk = blockIdx.x;
    int b   = blk >> 8;
    int pbase = blk*320;

    for (int i = tid; i < 4096; i += 320){
        int c = i >> 6, d = i & 63;
        w_s[d*64 + c] = W3[i];
    }
    if (tid < 64){
        float s  = d_stats[2*512 + b*64 + tid];
        float s2 = d_stats[3*512 + b*64 + tid];
        float mu = s * (1.f/(float)CNT);
        float var = s2 * (1.f/(float)CNT) - mu*mu;
        mean_s[tid] = mu;
        rstd_s[tid] = rsqrtf(var + EPSN);
        ssum[tid] = 0.f; ssq[tid] = 0.f;
    }
    __syncthreads();

    {
        int c4 = tid & 15, slot = tid >> 4;
        for (int it = 0; it < 16; it++){
            int p  = it*20 + slot;
            int gp = pbase + p;
            float4 hv = *(const float4*)(d_h2 + (size_t)gp*64 + c4*4);
            float h[4] = {hv.x, hv.y, hv.z, hv.w};
            #pragma unroll
            for (int q=0;q<4;q++){
                int c = c4*4+q;
                gbuf[c*GS + p] = leaky((h[q]-mean_s[c])*rstd_s[c]);
            }
        }
    }
    __syncthreads();

    int c0 = tx*8, p0 = ty*8;
    unsigned long long acc[8][4];
    #pragma unroll
    for (int i=0;i<8;i++)
        #pragma unroll
        for (int j=0;j<4;j++) acc[i][j] = 0ULL;

    for (int d = 0; d < 64; d++){
        float4 g0 = *(const float4*)(gbuf + d*GS + p0);
        float4 g1 = *(const float4*)(gbuf + d*GS + p0 + 4);
        ulonglong2 w0 = *(const ulonglong2*)(w_s + d*64 + c0);
        ulonglong2 w1 = *(const ulonglong2*)(w_s + d*64 + c0 + 4);
        float gg[8] = {g0.x,g0.y,g0.z,g0.w,g1.x,g1.y,g1.z,g1.w};
        #pragma unroll
        for (int i=0;i<8;i++){
            unsigned long long gd = dup2(gg[i]);
            acc[i][0] = ffma2(gd, w0.x, acc[i][0]);
            acc[i][1] = ffma2(gd, w0.y, acc[i][1]);
            acc[i][2] = ffma2(gd, w1.x, acc[i][2]);
            acc[i][3] = ffma2(gd, w1.y, acc[i][3]);
        }
    }

    float s[8], s2[8];
    #pragma unroll
    for (int j=0;j<8;j++){ s[j]=0.f; s2[j]=0.f; }
    float v[8][8];
    #pragma unroll
    for (int i=0;i<8;i++){
        #pragma unroll
        for (int j=0;j<4;j++) unpack2(acc[i][j], v[i][2*j], v[i][2*j+1]);
        #pragma unroll
        for (int j=0;j<8;j++){ float w = v[i][j]; s[j]+=w; s2[j]+=w*w; }
    }

    __syncthreads();   // all gbuf reads done before overwrite as hs

    #pragma unroll
    for (int i=0;i<8;i++){
        int p = p0 + i;
        *(float4*)(gbuf + p*HS + c0)     = make_float4(v[i][0],v[i][1],v[i][2],v[i][3]);
        *(float4*)(gbuf + p*HS + c0 + 4) = make_float4(v[i][4],v[i][5],v[i][6],v[i][7]);
    }
    #pragma unroll
    for (int j=0;j<8;j++){
        atomicAdd(&ssum[c0+j], s[j]);
        atomicAdd(&ssq [c0+j], s2[j]);
    }
    __syncthreads();

    if (tid < 64){
        atomicAdd(&d_stats[4*512 + b*64 + tid], ssum[tid]);
        atomicAdd(&d_stats[5*512 + b*64 + tid], ssq[tid]);
    }

    // max over k=20 within each of the 16 (b,n) groups of this block (pre-norm: monotone)
    for (int o = tid; o < 16*64; o += 320){
        int gi = o >> 6, c = o & 63;
        float mx = gbuf[(gi*20)*HS + c];
        #pragma unroll
        for (int j = 1; j < 20; j++)
            mx = fmaxf(mx, gbuf[(gi*20 + j)*HS + c]);
        d_h3max[(blk*16 + gi)*64 + c] = mx;
    }
}

// ---------------- K4: norm3 + leaky on maxed h3 -> output ----------------
__global__ void __launch_bounds__(256) k4(float* __restrict__ out){
    int g = blockIdx.x*256 + threadIdx.x;
    int c = g & 63;
    int b = g >> 18;                    // N*C = 262144 = 2^18 per batch
    float s  = d_stats[4*512 + b*64 + c];
    float s2 = d_stats[5*512 + b*64 + c];
    float mu = s * (1.f/(float)CNT);
    float var = s2 * (1.f/(float)CNT) - mu*mu;
    float r = rsqrtf(var + EPSN);
    out[g] = leaky((d_h3max[g] - mu)*r);
}

// ---------------- launch ----------------
extern "C" void kernel_launch(void* const* d_in, const int* in_sizes, int n_in,
                              void* d_out, int out_size){
    const float* x   = (const float*)d_in[0];
    const void*  ind = d_in[1];
    const float* W1  = (const float*)d_in[2];
    const float* W2  = (const float*)d_in[3];
    const float* W3  = (const float*)d_in[4];

    cudaFuncSetAttribute(k0, cudaFuncAttributeMaxDynamicSharedMemorySize, 50176);
    cudaFuncSetAttribute(k2, cudaFuncAttributeMaxDynamicSharedMemorySize, 104448);
    cudaFuncSetAttribute(k3, cudaFuncAttributeMaxDynamicSharedMemorySize, 104448);

    k_init  <<<6, 512>>>();
    k_detect<<<1, 32>>>((const int*)ind);
    k0      <<<512, dim3(16,16), 50176>>>(x, W1);
    k1      <<<1024, 256>>>(ind);
    k2      <<<2048, dim3(8,40), 104448>>>(ind, W2);
    k3      <<<2048, dim3(8,40), 104448>>>(W3);
    k4      <<<8192, 256>>>((float*)d_out);

    (void)in_sizes; (void)n_in; (void)out_size;
}

// round 3
// speedup vs baseline: 1.0466x; 1.0046x over previous
#include <cuda_runtime.h>

#define BB 8
#define NN 4096
#define DD 64
#define KK 20
#define CC 64
#define MM (BB*NN)          // 32768 points
#define PTS (MM*KK)         // 655360 (point, neighbor) pairs
#define CNT (NN*KK)         // 81920 values per (b, c) for instance norm
#define EPSN 1e-5f
#define SLOPE 0.01f
#define GS 324              // padded point-stride for transposed g tile
#define HS 68               // padded channel-stride for h3 tile

// ---------------- device scratch (static: allocation-free) ----------------
__device__ float d_P[MM*CC];        // x_flat @ W1a^T            (8 MB)
__device__ float d_U[MM*CC];        // x_flat @ (W1b - W1a)^T    (8 MB)
__device__ float d_h2[(size_t)PTS*CC];  // stage-2 pre-norm       (167 MB)
__device__ float d_h3max[MM*CC];    // max_k of pre-norm h3      (8 MB)
__device__ float d_stats[6*BB*CC];  // [sum1,sq1,sum2,sq2,sum3,sq3]
__device__ int   d_is64;

__device__ __forceinline__ float leaky(float v){ return fmaxf(v, SLOPE*v); }

__device__ __forceinline__ int load_ind(const void* ind, int p, int is64){
    if (is64) return (int)((const long long*)ind)[p];
    return ((const int*)ind)[p];
}

// ---- packed fp32x2 helpers (sm_100+): double-rate fp32 FMA, exact rn rounding ----
__device__ __forceinline__ unsigned long long ffma2(unsigned long long a,
                                                    unsigned long long b,
                                                    unsigned long long c){
    unsigned long long d;
    asm("fma.rn.f32x2 %0, %1, %2, %3;" : "=l"(d) : "l"(a), "l"(b), "l"(c));
    return d;
}
__device__ __forceinline__ unsigned long long dup2(float v){
    unsigned long long d;
    asm("mov.b64 %0, {%1, %1};" : "=l"(d) : "f"(v));
    return d;
}
__device__ __forceinline__ void unpack2(unsigned long long p, float& lo, float& hi){
    asm("mov.b64 {%0, %1}, %2;" : "=f"(lo), "=f"(hi) : "l"(p));
}

// ---------------- K_init: zero stats ----------------
__global__ void k_init(){
    int t = blockIdx.x*blockDim.x + threadIdx.x;
    if (t < 6*BB*CC) d_stats[t] = 0.f;
}

// ---------------- K_detect: int32 vs int64 indices ----------------
__global__ void k_detect(const int* ind32){
    if (threadIdx.x == 0 && blockIdx.x == 0){
        int is64 = 1;
        for (int i = 0; i < 128; i++){
            if (ind32[2*i + 1] != 0){ is64 = 0; break; }
        }
        d_is64 = is64;
    }
}

// ---------------- K0: P = x@W1a^T, U = x@(W1b-W1a)^T ----------------
__global__ void __launch_bounds__(256) k0(const float* __restrict__ x,
                                          const float* __restrict__ W1){
    extern __shared__ float sm[];
    float* xT = sm;             // 64 x 68
    float* Wa = sm + 64*68;     // [d][c]
    float* Wd = Wa + 4096;      // [d][c] = W1b - W1a

    int tid = threadIdx.y*16 + threadIdx.x;
    int m0  = blockIdx.x*64;

    for (int i = tid; i < 4096; i += 256){
        int c = i >> 6, d = i & 63;
        float a = W1[c*128 + d];
        float b = W1[c*128 + 64 + d];
        Wa[d*64 + c] = a;
        Wd[d*64 + c] = b - a;
    }
    for (int i = tid; i < 1024; i += 256){
        int r = i >> 4, c4 = i & 15;
        float4 v = *(const float4*)(x + (m0 + r)*64 + c4*4);
        xT[(c4*4+0)*68 + r] = v.x;
        xT[(c4*4+1)*68 + r] = v.y;
        xT[(c4*4+2)*68 + r] = v.z;
        xT[(c4*4+3)*68 + r] = v.w;
    }
    __syncthreads();

    int c0 = threadIdx.x*4, r0 = threadIdx.y*4;
    // packed: 4 rows x 2 channel-pairs for P and U
    unsigned long long accP[4][2], accU[4][2];
    #pragma unroll
    for (int i=0;i<4;i++){ accP[i][0]=0ULL; accP[i][1]=0ULL; accU[i][0]=0ULL; accU[i][1]=0ULL; }

    for (int d = 0; d < 64; d++){
        float4 xv = *(const float4*)(xT + d*68 + r0);
        ulonglong2 wa = *(const ulonglong2*)(Wa + d*64 + c0);
        ulonglong2 wd = *(const ulonglong2*)(Wd + d*64 + c0);
        float xs[4] = {xv.x, xv.y, xv.z, xv.w};
        #pragma unroll
        for (int i=0;i<4;i++){
            unsigned long long xd = dup2(xs[i]);
            accP[i][0] = ffma2(xd, wa.x, accP[i][0]);
            accP[i][1] = ffma2(xd, wa.y, accP[i][1]);
            accU[i][0] = ffma2(xd, wd.x, accU[i][0]);
            accU[i][1] = ffma2(xd, wd.y, accU[i][1]);
        }
    }
    #pragma unroll
    for (int i=0;i<4;i++){
        int row = (m0 + r0 + i)*64 + c0;
        float p0,p1,p2,p3,u0,u1,u2,u3;
        unpack2(accP[i][0], p0, p1); unpack2(accP[i][1], p2, p3);
        unpack2(accU[i][0], u0, u1); unpack2(accU[i][1], u2, u3);
        *(float4*)(d_P + row) = make_float4(p0,p1,p2,p3);
        *(float4*)(d_U + row) = make_float4(u0,u1,u2,u3);
    }
}

// ---------------- K1: stage-1 stats (sum, sumsq of h1 = P[idx]+U[m]) ----------------
__global__ void __launch_bounds__(256) k1(const void* __restrict__ ind_){
    __shared__ float ssum[64], ssq[64];
    int tid = threadIdx.x;
    int blk = blockIdx.x;
    int b   = blk >> 7;
    int is64 = d_is64;
    int c4 = tid & 15, slot = tid >> 4;   // 16 point-slots in flight
    int pbase = blk*640;

    float s[4] = {0,0,0,0}, s2[4] = {0,0,0,0};
    for (int it = 0; it < 40; it++){
        int gp = pbase + it*16 + slot;
        int idx = load_ind(ind_, gp, is64);
        int m = gp / KK;
        float4 pv = *(const float4*)(d_P + idx*64 + c4*4);
        float4 uv = *(const float4*)(d_U + m*64 + c4*4);
        float h[4] = {pv.x+uv.x, pv.y+uv.y, pv.z+uv.z, pv.w+uv.w};
        #pragma unroll
        for (int q=0;q<4;q++){ s[q] += h[q]; s2[q] += h[q]*h[q]; }
    }
    if (tid < 64){ ssum[tid] = 0.f; ssq[tid] = 0.f; }
    __syncthreads();
    #pragma unroll
    for (int q=0;q<4;q++){
        atomicAdd(&ssum[c4*4+q], s[q]);
        atomicAdd(&ssq [c4*4+q], s2[q]);
    }
    __syncthreads();
    if (tid < 64){
        atomicAdd(&d_stats[0*512 + b*64 + tid], ssum[tid]);
        atomicAdd(&d_stats[1*512 + b*64 + tid], ssq[tid]);
    }
}

// ---------------- K2: regather h1 -> norm1 -> leaky -> @W2^T -> h2 + stats2 ----------------
// grid 2048, block (8,40)=320 thr, tile 320 points x 64 ch, per-thread 8p x (4 ch-pairs)
__global__ void __launch_bounds__(320,2) k2(const void* __restrict__ ind_,
                                            const float* __restrict__ W2){
    extern __shared__ float sm[];
    float* w_s    = sm;                 // 4096: W2 transposed [d][c]
    float* gbuf   = sm + 4096;          // 64*GS transposed g tile
    float* mean_s = sm + 4096 + 21760;
    float* rstd_s = mean_s + 64;
    float* ssum   = rstd_s + 64;
    float* ssq    = ssum + 64;

    int tx = threadIdx.x, ty = threadIdx.y;
    int tid = ty*8 + tx;
    int blk = blockIdx.x;
    int b   = blk >> 8;                 // 256 blocks per batch
    int is64 = d_is64;
    int pbase = blk*320;

    for (int i = tid; i < 4096; i += 320){
        int c = i >> 6, d = i & 63;
        w_s[d*64 + c] = W2[i];
    }
    if (tid < 64){
        float s  = d_stats[0*512 + b*64 + tid];
        float s2 = d_stats[1*512 + b*64 + tid];
        float mu = s * (1.f/(float)CNT);
        float var = s2 * (1.f/(float)CNT) - mu*mu;
        mean_s[tid] = mu;
        rstd_s[tid] = rsqrtf(var + EPSN);
        ssum[tid] = 0.f; ssq[tid] = 0.f;
    }
    __syncthreads();

    // fill normalized+activated g, transposed [c][p]
    {
        int c4 = tid & 15, slot = tid >> 4;   // 20 slots
        for (int it = 0; it < 16; it++){
            int p  = it*20 + slot;
            int gp = pbase + p;
            int idx = load_ind(ind_, gp, is64);
            int m = gp / KK;
            float4 pv = *(const float4*)(d_P + idx*64 + c4*4);
            float4 uv = *(const float4*)(d_U + m*64 + c4*4);
            float h[4] = {pv.x+uv.x, pv.y+uv.y, pv.z+uv.z, pv.w+uv.w};
            #pragma unroll
            for (int q=0;q<4;q++){
                int c = c4*4+q;
                gbuf[c*GS + p] = leaky((h[q]-mean_s[c])*rstd_s[c]);
            }
        }
    }
    __syncthreads();

    int c0 = tx*8, p0 = ty*8;
    unsigned long long acc[8][4];
    #pragma unroll
    for (int i=0;i<8;i++)
        #pragma unroll
        for (int j=0;j<4;j++) acc[i][j] = 0ULL;

    for (int d = 0; d < 64; d++){
        float4 g0 = *(const float4*)(gbuf + d*GS + p0);
        float4 g1 = *(const float4*)(gbuf + d*GS + p0 + 4);
        ulonglong2 w0 = *(const ulonglong2*)(w_s + d*64 + c0);
        ulonglong2 w1 = *(const ulonglong2*)(w_s + d*64 + c0 + 4);
        float gg[8] = {g0.x,g0.y,g0.z,g0.w,g1.x,g1.y,g1.z,g1.w};
        #pragma unroll
        for (int i=0;i<8;i++){
            unsigned long long gd = dup2(gg[i]);
            acc[i][0] = ffma2(gd, w0.x, acc[i][0]);
            acc[i][1] = ffma2(gd, w0.y, acc[i][1]);
            acc[i][2] = ffma2(gd, w1.x, acc[i][2]);
            acc[i][3] = ffma2(gd, w1.y, acc[i][3]);
        }
    }

    float s[8], s2[8];
    #pragma unroll
    for (int j=0;j<8;j++){ s[j]=0.f; s2[j]=0.f; }
    #pragma unroll
    for (int i=0;i<8;i++){
        int gp = pbase + p0 + i;
        float v[8];
        #pragma unroll
        for (int j=0;j<4;j++) unpack2(acc[i][j], v[2*j], v[2*j+1]);
        *(float4*)(d_h2 + (size_t)gp*64 + c0)     = make_float4(v[0],v[1],v[2],v[3]);
        *(float4*)(d_h2 + (size_t)gp*64 + c0 + 4) = make_float4(v[4],v[5],v[6],v[7]);
        #pragma unroll
        for (int j=0;j<8;j++){ s[j]+=v[j]; s2[j]+=v[j]*v[j]; }
    }
    #pragma unroll
    for (int j=0;j<8;j++){
        atomicAdd(&ssum[c0+j], s[j]);
        atomicAdd(&ssq [c0+j], s2[j]);
    }
    __syncthreads();
    if (tid < 64){
        atomicAdd(&d_stats[2*512 + b*64 + tid], ssum[tid]);
        atomicAdd(&d_stats[3*512 + b*64 + tid], ssq[tid]);
    }
}

// ---------------- K3: h2 -> norm2 -> leaky -> @W3^T -> stats3 + max over k ----------------
__global__ void __launch_bounds__(320,2) k3(const float* __restrict__ W3){
    extern __shared__ float sm[];
    float* w_s    = sm;
    float* gbuf   = sm + 4096;          // matmul: 64*GS; then reused as hs: 320*HS
    float* mean_s = sm + 4096 + 21760;
    float* rstd_s = mean_s + 64;
    float* ssum   = rstd_s + 64;
    float* ssq    = ssum + 64;

    int tx = threadIdx.x, ty = threadIdx.y;
    int tid = ty*8 + tx;
    int blk = blockIdx.x;
    int b   = blk >> 8;
    int pbase = blk*320;

    for (int i = tid; i < 4096; i += 320){
        int c = i >> 6, d = i & 63;
        w_s[d*64 + c] = W3[i];
    }
    if (tid < 64){
        float s  = d_stats[2*512 + b*64 + tid];
        float s2 = d_stats[3*512 + b*64 + tid];
        float mu = s * (1.f/(float)CNT);
        float var = s2 * (1.f/(float)CNT) - mu*mu;
        mean_s[tid] = mu;
        rstd_s[tid] = rsqrtf(var + EPSN);
        ssum[tid] = 0.f; ssq[tid] = 0.f;
    }
    __syncthreads();

    {
        int c4 = tid & 15, slot = tid >> 4;
        for (int it = 0; it < 16; it++){
            int p  = it*20 + slot;
            int gp = pbase + p;
            float4 hv = *(const float4*)(d_h2 + (size_t)gp*64 + c4*4);
            float h[4] = {hv.x, hv.y, hv.z, hv.w};
            #pragma unroll
            for (int q=0;q<4;q++){
                int c = c4*4+q;
                gbuf[c*GS + p] = leaky((h[q]-mean_s[c])*rstd_s[c]);
            }
        }
    }
    __syncthreads();

    int c0 = tx*8, p0 = ty*8;
    unsigned long long acc[8][4];
    #pragma unroll
    for (int i=0;i<8;i++)
        #pragma unroll
        for (int j=0;j<4;j++) acc[i][j] = 0ULL;

    for (int d = 0; d < 64; d++){
        float4 g0 = *(const float4*)(gbuf + d*GS + p0);
        float4 g1 = *(const float4*)(gbuf + d*GS + p0 + 4);
        ulonglong2 w0 = *(const ulonglong2*)(w_s + d*64 + c0);
        ulonglong2 w1 = *(const ulonglong2*)(w_s + d*64 + c0 + 4);
        float gg[8] = {g0.x,g0.y,g0.z,g0.w,g1.x,g1.y,g1.z,g1.w};
        #pragma unroll
        for (int i=0;i<8;i++){
            unsigned long long gd = dup2(gg[i]);
            acc[i][0] = ffma2(gd, w0.x, acc[i][0]);
            acc[i][1] = ffma2(gd, w0.y, acc[i][1]);
            acc[i][2] = ffma2(gd, w1.x, acc[i][2]);
            acc[i][3] = ffma2(gd, w1.y, acc[i][3]);
        }
    }

    float s[8], s2[8];
    #pragma unroll
    for (int j=0;j<8;j++){ s[j]=0.f; s2[j]=0.f; }
    float v[8][8];
    #pragma unroll
    for (int i=0;i<8;i++){
        #pragma unroll
        for (int j=0;j<4;j++) unpack2(acc[i][j], v[i][2*j], v[i][2*j+1]);
        #pragma unroll
        for (int j=0;j<8;j++){ float w = v[i][j]; s[j]+=w; s2[j]+=w*w; }
    }

    __syncthreads();   // all gbuf reads done before overwrite as hs

    #pragma unroll
    for (int i=0;i<8;i++){
        int p = p0 + i;
        *(float4*)(gbuf + p*HS + c0)     = make_float4(v[i][0],v[i][1],v[i][2],v[i][3]);
        *(float4*)(gbuf + p*HS + c0 + 4) = make_float4(v[i][4],v[i][5],v[i][6],v[i][7]);
    }
    #pragma unroll
    for (int j=0;j<8;j++){
        atomicAdd(&ssum[c0+j], s[j]);
        atomicAdd(&ssq [c0+j], s2[j]);
    }
    __syncthreads();

    if (tid < 64){
        atomicAdd(&d_stats[4*512 + b*64 + tid], ssum[tid]);
        atomicAdd(&d_stats[5*512 + b*64 + tid], ssq[tid]);
    }

    // max over k=20 within each of the 16 (b,n) groups of this block (pre-norm: monotone)
    for (int o = tid; o < 16*64; o += 320){
        int gi = o >> 6, c = o & 63;
        float mx = gbuf[(gi*20)*HS + c];
        #pragma unroll
        for (int j = 1; j < 20; j++)
            mx = fmaxf(mx, gbuf[(gi*20 + j)*HS + c]);
        d_h3max[(blk*16 + gi)*64 + c] = mx;
    }
}

// ---------------- K4: norm3 + leaky on maxed h3 -> output ----------------
__global__ void __launch_bounds__(256) k4(float* __restrict__ out){
    int g = blockIdx.x*256 + threadIdx.x;
    int c = g & 63;
    int b = g >> 18;                    // N*C = 262144 = 2^18 per batch
    float s  = d_stats[4*512 + b*64 + c];
    float s2 = d_stats[5*512 + b*64 + c];
    float mu = s * (1.f/(float)CNT);
    float var = s2 * (1.f/(float)CNT) - mu*mu;
    float r = rsqrtf(var + EPSN);
    out[g] = leaky((d_h3max[g] - mu)*r);
}

// ---------------- launch ----------------
extern "C" void kernel_launch(void* const* d_in, const int* in_sizes, int n_in,
                              void* d_out, int out_size){
    const float* x   = (const float*)d_in[0];
    const void*  ind = d_in[1];
    const float* W1  = (const float*)d_in[2];
    const float* W2  = (const float*)d_in[3];
    const float* W3  = (const float*)d_in[4];

    cudaFuncSetAttribute(k0, cudaFuncAttributeMaxDynamicSharedMemorySize, 50176);
    cudaFuncSetAttribute(k2, cudaFuncAttributeMaxDynamicSharedMemorySize, 104448);
    cudaFuncSetAttribute(k3, cudaFuncAttributeMaxDynamicSharedMemorySize, 104448);

    k_init  <<<6, 512>>>();
    k_detect<<<1, 32>>>((const int*)ind);
    k0      <<<512, dim3(16,16), 50176>>>(x, W1);
    k1      <<<1024, 256>>>(ind);
    k2      <<<2048, dim3(8,40), 104448>>>(ind, W2);
    k3      <<<2048, dim3(8,40), 104448>>>(W3);
    k4      <<<8192, 256>>>((float*)d_out);

    (void)in_sizes; (void)n_in; (void)out_size;
}